// round 1
// baseline (speedup 1.0000x reference)
#include <cuda_runtime.h>
#include <math.h>

// Problem constants
#define BB   32
#define SS   256
#define NN   50
#define DD   100
#define QDIM 768

// Scratch for normalized Q projection (no cudaMalloc allowed)
__device__ float g_Qn[BB * DD];

// ---------------------------------------------------------------------------
// Kernel 1: Q = q @ Q_w^T + Q_b ; Qn = Q / max(||Q||, 1e-12)
// grid = 32 (one per batch), block = 256
// ---------------------------------------------------------------------------
__global__ __launch_bounds__(256) void qproj_kernel(
    const float* __restrict__ q,
    const float* __restrict__ Qw,
    const float* __restrict__ Qb)
{
    int b = blockIdx.x;
    __shared__ float sq[QDIM];
    __shared__ float sQ[DD];
    __shared__ float red[8];

    int tid  = threadIdx.x;
    int warp = tid >> 5;
    int lane = tid & 31;

    for (int j = tid; j < QDIM; j += 256) sq[j] = q[b * QDIM + j];
    __syncthreads();

    // each warp computes dots for e = warp, warp+8, ...
    for (int e = warp; e < DD; e += 8) {
        const float* wrow = Qw + (size_t)e * QDIM;
        float acc = 0.f;
        for (int j = lane; j < QDIM; j += 32) acc += sq[j] * wrow[j];
        #pragma unroll
        for (int o = 16; o; o >>= 1) acc += __shfl_xor_sync(0xffffffffu, acc, o);
        if (lane == 0) sQ[e] = acc + Qb[e];
    }
    __syncthreads();

    // norm over 100 elements
    float ss = 0.f;
    for (int e = tid; e < DD; e += 256) ss += sQ[e] * sQ[e];
    #pragma unroll
    for (int o = 16; o; o >>= 1) ss += __shfl_xor_sync(0xffffffffu, ss, o);
    if (lane == 0) red[warp] = ss;
    __syncthreads();
    if (tid == 0) {
        float t = 0.f;
        #pragma unroll
        for (int w = 0; w < 8; w++) t += red[w];
        red[0] = fmaxf(sqrtf(t), 1e-12f);
    }
    __syncthreads();
    float inv = 1.0f / red[0];
    for (int e = tid; e < DD; e += 256) g_Qn[b * DD + e] = sQ[e] * inv;
}

// ---------------------------------------------------------------------------
// Kernel 2: per-(b,s) fused attention
//   K[n,e]   = sum_d v[b,s,n,d] * V_w[e,d] + V_b[e]
//   score[n] = (Qn_b . K[n]) / max-ish(||K[n]||)   (with ==0 -> 1e-6)
//   att      = softmax(leaky_relu(where(score==0,-1e4,score), 0.01))
//   att      = where(att == 1/50, 0)
//   out[b,s] = sum_n att[n] * K[n,:]
// grid = B*S = 8192, block = 256, dyn smem ~81KB
// ---------------------------------------------------------------------------
#define SMEM_FLOATS (10000 + 5000 + 5000 + 100 + 100 + 64)

__global__ __launch_bounds__(256) void attn_kernel(
    const float* __restrict__ v,
    const float* __restrict__ Vw,
    const float* __restrict__ Vb,
    float* __restrict__ out)
{
    extern __shared__ float smem[];
    float* sWt  = smem;               // [100][100]  W^T: sWt[d*100+e] = Vw[e*100+d]
    float* sV   = smem + 10000;       // [50][100]
    float* sK   = smem + 15000;       // [50][100]
    float* sVb  = smem + 20000;       // [100]
    float* sQn  = smem + 20100;       // [100]
    float* sAtt = smem + 20200;       // [50]

    int bs  = blockIdx.x;             // b*S + s
    int b   = bs / SS;
    int tid = threadIdx.x;

    // --- stage V_w transposed, bias, Qn ---
    for (int i = tid; i < DD * DD; i += 256) {
        int e = i / DD, d = i % DD;         // coalesced read of Vw
        sWt[d * DD + e] = Vw[i];
    }
    if (tid < DD) { sVb[tid] = Vb[tid]; sQn[tid] = g_Qn[b * DD + tid]; }

    // --- stage v tile (5000 floats, float4) ---
    {
        const float4* vsrc = (const float4*)(v + (size_t)bs * (NN * DD));
        float4* vdst = (float4*)sV;
        for (int i = tid; i < (NN * DD) / 4; i += 256) vdst[i] = vsrc[i];
    }
    __syncthreads();

    // --- GEMM: K[50x100] = sV[50x100] @ sWt + Vb ; 250 threads, 5x4 tiles ---
    if (tid < 250) {
        int n0 = (tid / 25) * 5;      // 0,5,...,45
        int e0 = (tid % 25) * 4;      // 0,4,...,96
        float acc[5][4];
        #pragma unroll
        for (int i = 0; i < 5; i++)
            #pragma unroll
            for (int j = 0; j < 4; j++) acc[i][j] = 0.f;

        #pragma unroll 2
        for (int d = 0; d < DD; d++) {
            float4 bv = *(const float4*)&sWt[d * DD + e0];
            float a0 = sV[(n0 + 0) * DD + d];
            float a1 = sV[(n0 + 1) * DD + d];
            float a2 = sV[(n0 + 2) * DD + d];
            float a3 = sV[(n0 + 3) * DD + d];
            float a4 = sV[(n0 + 4) * DD + d];
            acc[0][0] += a0 * bv.x; acc[0][1] += a0 * bv.y; acc[0][2] += a0 * bv.z; acc[0][3] += a0 * bv.w;
            acc[1][0] += a1 * bv.x; acc[1][1] += a1 * bv.y; acc[1][2] += a1 * bv.z; acc[1][3] += a1 * bv.w;
            acc[2][0] += a2 * bv.x; acc[2][1] += a2 * bv.y; acc[2][2] += a2 * bv.z; acc[2][3] += a2 * bv.w;
            acc[3][0] += a3 * bv.x; acc[3][1] += a3 * bv.y; acc[3][2] += a3 * bv.z; acc[3][3] += a3 * bv.w;
            acc[4][0] += a4 * bv.x; acc[4][1] += a4 * bv.y; acc[4][2] += a4 * bv.z; acc[4][3] += a4 * bv.w;
        }
        #pragma unroll
        for (int i = 0; i < 5; i++)
            #pragma unroll
            for (int j = 0; j < 4; j++)
                sK[(n0 + i) * DD + (e0 + j)] = acc[i][j] + sVb[e0 + j];
    }
    __syncthreads();

    // --- scores: per-n fused ||K|| and Qn.K ; warp per n (strided) ---
    int warp = tid >> 5, lane = tid & 31;
    for (int n = warp; n < NN; n += 8) {
        float ss = 0.f, qk = 0.f;
        for (int e = lane; e < DD; e += 32) {
            float kk = sK[n * DD + e];
            ss += kk * kk;
            qk += sQn[e] * kk;
        }
        #pragma unroll
        for (int o = 16; o; o >>= 1) {
            ss += __shfl_xor_sync(0xffffffffu, ss, o);
            qk += __shfl_xor_sync(0xffffffffu, qk, o);
        }
        if (lane == 0) {
            float l2 = sqrtf(ss);
            if (l2 == 0.0f) l2 = 1e-6f;
            sAtt[n] = qk / l2;
        }
    }
    __syncthreads();

    // --- softmax over 50 neighbors (warp 0) ---
    if (warp == 0) {
        float x0 = sAtt[lane];                 // n = lane (<32, all valid)
        x0 = (x0 == 0.0f) ? -10000.0f : x0;
        x0 = (x0 > 0.0f) ? x0 : 0.01f * x0;
        float x1 = -INFINITY;
        if (lane < NN - 32) {
            x1 = sAtt[lane + 32];
            x1 = (x1 == 0.0f) ? -10000.0f : x1;
            x1 = (x1 > 0.0f) ? x1 : 0.01f * x1;
        }
        float m = fmaxf(x0, x1);
        #pragma unroll
        for (int o = 16; o; o >>= 1) m = fmaxf(m, __shfl_xor_sync(0xffffffffu, m, o));
        float e0 = expf(x0 - m);
        float e1 = (lane < NN - 32) ? expf(x1 - m) : 0.0f;
        float s = e0 + e1;
        #pragma unroll
        for (int o = 16; o; o >>= 1) s += __shfl_xor_sync(0xffffffffu, s, o);
        float inv = 1.0f / s;
        float a0 = e0 * inv;
        if (a0 == (1.0f / 50.0f)) a0 = 0.0f;
        sAtt[lane] = a0;
        if (lane < NN - 32) {
            float a1 = e1 * inv;
            if (a1 == (1.0f / 50.0f)) a1 = 0.0f;
            sAtt[lane + 32] = a1;
        }
    }
    __syncthreads();

    // --- output: out[bs, e] = sum_n att[n] * K[n, e] ---
    if (tid < DD) {
        float o = 0.f;
        #pragma unroll
        for (int n = 0; n < NN; n++) o += sAtt[n] * sK[n * DD + tid];
        out[(size_t)bs * DD + tid] = o;
    }
}

// ---------------------------------------------------------------------------
extern "C" void kernel_launch(void* const* d_in, const int* in_sizes, int n_in,
                              void* d_out, int out_size)
{
    // metadata order: input_ent, q, k, v, Q_w, Q_b, V_w, V_b
    const float* q  = (const float*)d_in[1];
    const float* v  = (const float*)d_in[3];
    const float* Qw = (const float*)d_in[4];
    const float* Qb = (const float*)d_in[5];
    const float* Vw = (const float*)d_in[6];
    const float* Vb = (const float*)d_in[7];
    float* out = (float*)d_out;

    qproj_kernel<<<BB, 256>>>(q, Qw, Qb);

    size_t smem_bytes = SMEM_FLOATS * sizeof(float);
    cudaFuncSetAttribute(attn_kernel, cudaFuncAttributeMaxDynamicSharedMemorySize,
                         (int)smem_bytes);
    attn_kernel<<<BB * SS, 256, smem_bytes>>>(v, Vw, Vb, out);
}

// round 2
// speedup vs baseline: 1.8436x; 1.8436x over previous
#include <cuda_runtime.h>
#include <math.h>

#define BB   32
#define SS   256
#define NN   50
#define DD   100
#define QDIM 768

#define AP 108          // sV row stride (floats) -> conflict-free A frags
#define BP 104          // sWt row stride (floats) -> conflict-free B frags
#define MROWS 112       // padded M (2 s * 50 rows -> 112)
#define KP 104          // padded K
#define NP 104          // padded N

// per-batch precomputed: w~ = W^T Qn  [B][100], c = Qn . V_b  [B]
__device__ float g_wt[BB * DD];
__device__ float g_cb[BB];

// ---------------------------------------------------------------------------
// Kernel 1: Qn = normalize(q @ Qw^T + Qb); g_wt = Vw^T Qn ; g_cb = Qn . Vb
// ---------------------------------------------------------------------------
__global__ __launch_bounds__(256) void qproj_kernel(
    const float* __restrict__ q,
    const float* __restrict__ Qw,
    const float* __restrict__ Qb,
    const float* __restrict__ Vw,
    const float* __restrict__ Vb)
{
    int b = blockIdx.x;
    __shared__ float sq[QDIM];
    __shared__ float sQ[DD];
    __shared__ float red[8];

    int tid  = threadIdx.x;
    int warp = tid >> 5;
    int lane = tid & 31;

    for (int j = tid; j < QDIM; j += 256) sq[j] = q[b * QDIM + j];
    __syncthreads();

    for (int e = warp; e < DD; e += 8) {
        const float* wrow = Qw + (size_t)e * QDIM;
        float acc = 0.f;
        for (int j = lane; j < QDIM; j += 32) acc += sq[j] * wrow[j];
        #pragma unroll
        for (int o = 16; o; o >>= 1) acc += __shfl_xor_sync(0xffffffffu, acc, o);
        if (lane == 0) sQ[e] = acc + Qb[e];
    }
    __syncthreads();

    float ss = 0.f;
    for (int e = tid; e < DD; e += 256) ss += sQ[e] * sQ[e];
    #pragma unroll
    for (int o = 16; o; o >>= 1) ss += __shfl_xor_sync(0xffffffffu, ss, o);
    if (lane == 0) red[warp] = ss;
    __syncthreads();
    if (tid == 0) {
        float t = 0.f;
        #pragma unroll
        for (int w = 0; w < 8; w++) t += red[w];
        red[0] = fmaxf(sqrtf(t), 1e-12f);
    }
    __syncthreads();
    float inv = 1.0f / red[0];
    for (int e = tid; e < DD; e += 256) sQ[e] *= inv;   // sQ = Qn
    __syncthreads();

    // w~_d = sum_e Qn[e] * Vw[e*100+d]   (coalesced over d)
    for (int d = tid; d < DD; d += 256) {
        float acc = 0.f;
        #pragma unroll 4
        for (int e = 0; e < DD; e++) acc += sQ[e] * Vw[e * DD + d];
        g_wt[b * DD + d] = acc;
    }
    // c_b = Qn . Vb
    if (warp == 0) {
        float acc = 0.f;
        for (int e = lane; e < DD; e += 32) acc += sQ[e] * Vb[e];
        #pragma unroll
        for (int o = 16; o; o >>= 1) acc += __shfl_xor_sync(0xffffffffu, acc, o);
        if (lane == 0) g_cb[b] = acc;
    }
}

// ---------------------------------------------------------------------------
// tf32 mma m16n8k8 (raw fp32 bits; HW truncates to tf32)
// ---------------------------------------------------------------------------
__device__ __forceinline__ void mma_tf32(float c[4], const float a[4],
                                         float b0, float b1)
{
    asm volatile(
        "mma.sync.aligned.m16n8k8.row.col.f32.tf32.tf32.f32 "
        "{%0,%1,%2,%3}, {%4,%5,%6,%7}, {%8,%9}, {%0,%1,%2,%3};\n"
        : "+f"(c[0]), "+f"(c[1]), "+f"(c[2]), "+f"(c[3])
        : "r"(__float_as_uint(a[0])), "r"(__float_as_uint(a[1])),
          "r"(__float_as_uint(a[2])), "r"(__float_as_uint(a[3])),
          "r"(__float_as_uint(b0)),  "r"(__float_as_uint(b1)));
}

// ---------------------------------------------------------------------------
// Kernel 2: block = (b, s-pair). Warps 0..6: tf32 GEMM -> row norms^2 of
// K = v@W^T + b. Warp 7: exact fp32 score numerators. Epilogue (fp32 exact):
// softmax -> t = att@v -> out = W t + sigma*b.
// ---------------------------------------------------------------------------
#define SMEM_FLOATS (MROWS*AP + KP*BP + 100 + 100 + MROWS + 100 + 100 + 200 + 8)

__global__ __launch_bounds__(256, 2) void attn_kernel(
    const float* __restrict__ v,
    const float* __restrict__ Vw,
    const float* __restrict__ Vb,
    float* __restrict__ out)
{
    extern __shared__ float smem[];
    float* sV    = smem;                    // [112][108] rows 0..99 = v (2 s)
    float* sWt   = sV   + MROWS * AP;       // [104][104] sWt[d][e] = W[e][d]
    float* sVb   = sWt  + KP * BP;          // [100]
    float* sWq   = sVb  + 100;              // [100] w~
    float* snorm = sWq  + 100;              // [112] row norms^2
    float* sdot  = snorm + MROWS;           // [100] score numerators
    float* sAtt  = sdot + 100;              // [100] (2 x 50)
    float* st    = sAtt + 100;              // [200] t vectors
    float* sMisc = st   + 200;              // [0]=sig0 [1]=sig1 [2]=c_b

    int tid  = threadIdx.x;
    int warp = tid >> 5;
    int lane = tid & 31;
    int g    = lane >> 2;
    int tg   = lane & 3;

    int blk = blockIdx.x;                   // 4096 blocks: b*128 + spair
    int b   = blk >> 7;
    size_t base = (size_t)blk * 10000;      // 2 consecutive (b,s) tiles

    // zero padded tiles
    for (int i = tid; i < MROWS * AP; i += 256) sV[i] = 0.f;
    for (int i = tid; i < KP * BP;    i += 256) sWt[i] = 0.f;
    __syncthreads();

    // stage: v rows (row = s_local*50 + n), W^T, bias, per-batch vectors
    for (int i = tid; i < 10000; i += 256) {
        int r = i / 100, c = i - r * 100;
        sV[r * AP + c] = v[base + i];
    }
    for (int i = tid; i < 10000; i += 256) {
        int e = i / 100, d = i - e * 100;
        sWt[d * BP + e] = Vw[i];
    }
    if (tid < 100) { sVb[tid] = Vb[tid]; sWq[tid] = g_wt[b * DD + tid]; }
    if (tid == 224) sMisc[2] = g_cb[b];
    __syncthreads();

    if (warp < 7) {
        // ---- tf32 GEMM for row norms^2 ----
        int mrow = warp * 16 + g;
        const float* a0p = sV + mrow * AP;
        const float* a1p = sV + (mrow + 8) * AP;
        float aR[13][4];
        #pragma unroll
        for (int kt = 0; kt < 13; kt++) {
            int k0 = kt * 8;
            aR[kt][0] = a0p[k0 + tg];
            aR[kt][1] = a1p[k0 + tg];
            aR[kt][2] = a0p[k0 + tg + 4];
            aR[kt][3] = a1p[k0 + tg + 4];
        }
        float sq0 = 0.f, sq1 = 0.f;
        #pragma unroll 1
        for (int nt = 0; nt < 13; nt++) {
            int n0 = nt * 8;
            float c[4] = {0.f, 0.f, 0.f, 0.f};
            const float* bB = sWt + n0 + g;
            #pragma unroll
            for (int kt = 0; kt < 13; kt++) {
                float b0 = bB[(kt * 8 + tg) * BP];
                float b1 = bB[(kt * 8 + tg + 4) * BP];
                mma_tf32(c, aR[kt], b0, b1);
            }
            int col0 = n0 + 2 * tg;
            if (col0 < 100) {
                float bia = sVb[col0];
                float k0v = c[0] + bia; sq0 += k0v * k0v;
                float k2v = c[2] + bia; sq1 += k2v * k2v;
            }
            if (col0 + 1 < 100) {
                float bia = sVb[col0 + 1];
                float k1v = c[1] + bia; sq0 += k1v * k1v;
                float k3v = c[3] + bia; sq1 += k3v * k3v;
            }
        }
        sq0 += __shfl_xor_sync(0xffffffffu, sq0, 1);
        sq0 += __shfl_xor_sync(0xffffffffu, sq0, 2);
        sq1 += __shfl_xor_sync(0xffffffffu, sq1, 1);
        sq1 += __shfl_xor_sync(0xffffffffu, sq1, 2);
        if (tg == 0) { snorm[mrow] = sq0; snorm[mrow + 8] = sq1; }
    } else {
        // ---- exact fp32 numerators: sdot[r] = w~ . v_r + c_b ----
        float cb = sMisc[2];
        for (int r = lane; r < 100; r += 32) {
            const float* vr = sV + r * AP;
            float acc = cb;
            #pragma unroll 4
            for (int d = 0; d < DD; d++) acc += sWq[d] * vr[d];
            sdot[r] = acc;
        }
    }
    __syncthreads();

    // ---- softmax per s (warps 0,1) ----
    if (warp < 2) {
        int s = warp;
        int rb = s * 50;

        float x0, x1;
        {
            int r = rb + lane;
            float l2 = sqrtf(snorm[r]);
            if (l2 == 0.0f) l2 = 1e-6f;
            float sc = sdot[r] / l2;
            sc = (sc == 0.0f) ? -10000.0f : sc;
            x0 = (sc > 0.0f) ? sc : 0.01f * sc;
        }
        x1 = -INFINITY;
        if (lane < NN - 32) {
            int r = rb + lane + 32;
            float l2 = sqrtf(snorm[r]);
            if (l2 == 0.0f) l2 = 1e-6f;
            float sc = sdot[r] / l2;
            sc = (sc == 0.0f) ? -10000.0f : sc;
            x1 = (sc > 0.0f) ? sc : 0.01f * sc;
        }
        float m = fmaxf(x0, x1);
        #pragma unroll
        for (int o = 16; o; o >>= 1) m = fmaxf(m, __shfl_xor_sync(0xffffffffu, m, o));
        float e0 = expf(x0 - m);
        float e1 = (lane < NN - 32) ? expf(x1 - m) : 0.0f;
        float sm = e0 + e1;
        #pragma unroll
        for (int o = 16; o; o >>= 1) sm += __shfl_xor_sync(0xffffffffu, sm, o);
        float inv = 1.0f / sm;
        float a0 = e0 * inv;
        if (a0 == (1.0f / 50.0f)) a0 = 0.0f;
        float a1 = 0.0f;
        if (lane < NN - 32) {
            a1 = e1 * inv;
            if (a1 == (1.0f / 50.0f)) a1 = 0.0f;
        }
        sAtt[rb + lane] = a0;
        if (lane < NN - 32) sAtt[rb + lane + 32] = a1;
        // sigma = sum of final att
        float sg = a0 + a1;
        #pragma unroll
        for (int o = 16; o; o >>= 1) sg += __shfl_xor_sync(0xffffffffu, sg, o);
        if (lane == 0) sMisc[s] = sg;
    }
    __syncthreads();

    // ---- t[s][d] = sum_n att[s][n] * v[s][n][d] ----
    int s = tid >> 7;          // 0 or 1
    int d = tid & 127;
    if (d < 100) {
        float acc = 0.f;
        const float* vb = sV + (s * 50) * AP + d;
        const float* ab = sAtt + s * 50;
        #pragma unroll 5
        for (int n = 0; n < NN; n++) acc += ab[n] * vb[n * AP];
        st[s * 100 + d] = acc;
    }
    __syncthreads();

    // ---- out[s][e] = sum_d t[s][d]*W[e][d] + sigma*b[e] = sum_d t_d sWt[d][e] + ...
    if (d < 100) {
        float acc = sMisc[s] * sVb[d];
        const float* tp = st + s * 100;
        #pragma unroll 4
        for (int dd = 0; dd < DD; dd++) acc += tp[dd] * sWt[dd * BP + d];
        out[(size_t)blk * 200 + s * 100 + d] = acc;
    }
}

// ---------------------------------------------------------------------------
extern "C" void kernel_launch(void* const* d_in, const int* in_sizes, int n_in,
                              void* d_out, int out_size)
{
    // metadata order: input_ent, q, k, v, Q_w, Q_b, V_w, V_b
    const float* q  = (const float*)d_in[1];
    const float* v  = (const float*)d_in[3];
    const float* Qw = (const float*)d_in[4];
    const float* Qb = (const float*)d_in[5];
    const float* Vw = (const float*)d_in[6];
    const float* Vb = (const float*)d_in[7];
    float* out = (float*)d_out;

    qproj_kernel<<<BB, 256>>>(q, Qw, Qb, Vw, Vb);

    size_t smem_bytes = SMEM_FLOATS * sizeof(float);
    cudaFuncSetAttribute(attn_kernel, cudaFuncAttributeMaxDynamicSharedMemorySize,
                         (int)smem_bytes);
    attn_kernel<<<BB * SS / 2, 256, smem_bytes>>>(v, Vw, Vb, out);
}